// round 1
// baseline (speedup 1.0000x reference)
#include <cuda_runtime.h>

#define Hh 256
#define Ww 256
#define Bn 8
#define Fn 64
#define HW 65536
#define TR 8          // rows per tile in pass1/pass2
#define PBLK 128      // blocks in power kernel (co-resident <= 148 SMs)

// ---------------- device globals (scratch; no allocations allowed) ----------
__device__ float g_xA[HW];
__device__ float g_xB[HW];
__device__ float g_part[2][PBLK];
__device__ float g_K[81];   // K[a9][b9], a9=(ai*3+aj), b9=(bi*3+bj), a,b in [-1,1]^2 offset by +1
__device__ float g_G[25];   // composed 5x5 kernel
__device__ float g_sigma, g_beta, g_lambda, g_tau, g_lip2;
__device__ unsigned g_barcnt = 0;   // invariant: 0 between barriers (survives graph replay)
__device__ unsigned g_bargen = 0;   // monotonically increasing generation

// ---------------- setup: tables + scalars + x0 ------------------------------
__global__ void k_setup(const float* __restrict__ w, const float* __restrict__ beta,
                        const float* __restrict__ lambd, const float* __restrict__ lsig)
{
    if (blockIdx.x == 0) {
        __shared__ float sK[81];
        int t = threadIdx.x;
        if (t < 81) {
            int a9 = t / 9, b9 = t % 9;
            int ai = a9 / 3, aj = a9 % 3;
            int bi = b9 / 3, bj = b9 % 3;
            float s = 0.f;
            #pragma unroll 8
            for (int f = 0; f < Fn; f++)
                s += w[f*9 + (2-ai)*3 + (2-aj)] * w[f*9 + bi*3 + bj];
            sK[t] = s;
            g_K[t] = s;
        }
        __syncthreads();
        if (t < 25) {
            int di = t / 5 - 2, dj = t % 5 - 2;
            float s = 0.f;
            for (int a9 = 0; a9 < 9; a9++) {
                int ai = a9/3 - 1, aj = a9%3 - 1;
                int bi = di - ai, bj = dj - aj;
                if (bi >= -1 && bi <= 1 && bj >= -1 && bj <= 1)
                    s += sK[a9*9 + (bi+1)*3 + (bj+1)];
            }
            g_G[t] = s;
        }
        if (t == 0) {
            g_sigma  = expf(lsig[0]) + 0.05f;
            g_beta   = beta[0];
            g_lambda = lambd[0];
        }
    } else {
        // fill x0 = ones / ||ones|| = 1/256
        int p = (blockIdx.x - 1) * 512 + threadIdx.x;
        g_xA[p]       = 1.f / 256.f;
        g_xA[p + 256] = 1.f / 256.f;
    }
}

// ---------------- software grid barrier (graph-replay safe) -----------------
__device__ __forceinline__ void grid_bar()
{
    __syncthreads();
    if (threadIdx.x == 0) {
        __threadfence();                       // flush dst + partials to L2
        volatile unsigned* genp = &g_bargen;
        unsigned gen = *genp;                  // cannot advance until we arrive
        unsigned a = atomicAdd(&g_barcnt, 1u);
        if (a == PBLK - 1u) {
            atomicExch(&g_barcnt, 0u);         // reset BEFORE releasing
            __threadfence();
            atomicExch(&g_bargen, gen + 1u);
        } else {
            while (*genp == gen) { __nanosleep(32); }
        }
        __threadfence();
    }
    __syncthreads();
}

// ---------------- power iteration: lip2 = ||conv_t(conv(.))|| ---------------
__global__ void k_power()
{
    __shared__ float red[256];
    const int t = threadIdx.x, blk = blockIdx.x;
    const int i0 = blk * 2, j = t;

    float G[25];
    #pragma unroll
    for (int k = 0; k < 25; k++) G[k] = g_G[k];   // L1 fresh per launch

    float val = 1.f, inv = 1.f;
    int iter = 0;

    while (true) {
        const float* src = (iter & 1) ? g_xB : g_xA;
        float*       dst = (iter & 1) ? g_xA : g_xB;
        float s2 = 0.f;

        #pragma unroll
        for (int pp = 0; pp < 2; pp++) {
            const int i = i0 + pp;
            float z = 0.f;
            // interior: composed 5x5 kernel (exact for pixels not on the border)
            #pragma unroll
            for (int di = -2; di <= 2; di++) {
                int ii = i + di;
                if (ii < 0 || ii > 255) continue;
                #pragma unroll
                for (int dj = -2; dj <= 2; dj++) {
                    int jj = j + dj;
                    if (jj < 0 || jj > 255) continue;
                    z = fmaf(G[(di+2)*5 + (dj+2)], __ldcg(&src[ii*256 + jj]), z);
                }
            }
            // border correction: subtract terms whose intermediate y-pixel was
            // outside the grid (zeroed by the conv padding in the reference)
            if (i == 0 || i == 255 || j == 0 || j == 255) {
                #pragma unroll
                for (int ai = 0; ai < 3; ai++) {
                    #pragma unroll
                    for (int aj = 0; aj < 3; aj++) {
                        int pi = i + ai - 1, pj = j + aj - 1;
                        if (pi < 0 || pi > 255 || pj < 0 || pj > 255) {
                            #pragma unroll
                            for (int bi = 0; bi < 3; bi++) {
                                #pragma unroll
                                for (int bj = 0; bj < 3; bj++) {
                                    int qi = pi + bi - 1, qj = pj + bj - 1;
                                    if (qi >= 0 && qi < 256 && qj >= 0 && qj < 256)
                                        z -= g_K[(ai*3+aj)*9 + bi*3+bj] *
                                             __ldcg(&src[qi*256 + qj]);
                                }
                            }
                        }
                    }
                }
            }
            z *= inv;                       // apply deferred normalization
            dst[i*256 + j] = z;
            s2 = fmaf(z, z, s2);
        }

        // deterministic block reduce
        red[t] = s2; __syncthreads();
        #pragma unroll
        for (int s = 128; s > 0; s >>= 1) {
            if (t < s) red[t] += red[t + s];
            __syncthreads();
        }
        if (t == 0) g_part[iter & 1][blk] = red[0];

        grid_bar();

        // deterministic fixed-order global sum (identical on every thread)
        float tot = 0.f;
        #pragma unroll 8
        for (int b2 = 0; b2 < PBLK; b2++) tot += __ldcg(&g_part[iter & 1][b2]);
        float v2  = sqrtf(tot);
        float rel = fabsf(v2 - val) / val;
        val = v2;
        inv = 1.f / v2;
        iter++;
        if (iter >= 300 || rel < 1e-4f) break;   // exact while_loop semantics
    }

    if (blk == 0 && t == 0) {
        g_lip2 = val;
        g_tau  = 0.99f / (g_beta * 0.5f + g_sigma * val);
    }
}

// ---------------- pass 1: out0 ----------------------------------------------
__global__ void k_pass1(const float* __restrict__ x_in,
                        const float* __restrict__ u_in,
                        const float* __restrict__ bias,
                        const float* __restrict__ HtH,
                        const float* __restrict__ w,
                        float* __restrict__ out0)
{
    __shared__ float su[TR + 2][Ww + 2];
    const int t    = threadIdx.x;
    const int b    = blockIdx.x >> 5;       // 32 tiles per batch
    const int tile = blockIdx.x & 31;
    const int i0   = tile * TR;
    const float tau = g_tau;

    float acc[TR];
    #pragma unroll
    for (int r = 0; r < TR; r++) {
        int hw = (i0 + r) * Ww + t;
        float xv = x_in[b*HW + hw];
        acc[r] = xv - tau * (HtH[hw] * xv) + tau * bias[b*HW + hw];
    }
    if (t < TR + 2) { su[t][0] = 0.f; su[t][Ww + 1] = 0.f; }

    for (int f = 0; f < Fn; f++) {
        __syncthreads();
        #pragma unroll
        for (int rr = 0; rr < TR + 2; rr++) {
            int gi = i0 + rr - 1;
            su[rr][t + 1] = (gi >= 0 && gi < Hh)
                          ? u_in[((b*Fn + f)*Hh + gi)*Ww + t] : 0.f;
        }
        __syncthreads();

        float m[3][3];
        #pragma unroll
        for (int au = 0; au < 3; au++)
            #pragma unroll
            for (int ac = 0; ac < 3; ac++)
                m[au][ac] = tau * __ldg(&w[f*9 + (2-au)*3 + (2-ac)]);

        #pragma unroll
        for (int ac = 0; ac < 3; ac++) {
            #pragma unroll
            for (int rr = 0; rr < TR + 2; rr++) {
                float v = su[rr][t + ac];
                if (rr < TR)               acc[rr]   = fmaf(-m[0][ac], v, acc[rr]);
                if (rr >= 1 && rr < TR+1)  acc[rr-1] = fmaf(-m[1][ac], v, acc[rr-1]);
                if (rr >= 2)               acc[rr-2] = fmaf(-m[2][ac], v, acc[rr-2]);
            }
        }
    }

    #pragma unroll
    for (int r = 0; r < TR; r++) {
        float o = fminf(fmaxf(acc[r], 0.f), 1.f);
        out0[b*HW + (i0 + r)*Ww + t] = o;
    }
}

// ---------------- pass 2: out1 ----------------------------------------------
__global__ void k_pass2(const float* __restrict__ x_in,
                        const float* __restrict__ u_in,
                        const float* __restrict__ w,
                        const float* __restrict__ out0,
                        float* __restrict__ out1)
{
    __shared__ float st[TR + 2][Ww + 2];
    const int t    = threadIdx.x;
    const int b    = blockIdx.x >> 5;
    const int tile = blockIdx.x & 31;
    const int i0   = tile * TR;
    const float sig = g_sigma, lam = g_lambda;

    if (t < TR + 2) { st[t][0] = 0.f; st[t][Ww + 1] = 0.f; }
    #pragma unroll
    for (int rr = 0; rr < TR + 2; rr++) {
        int gi = i0 + rr - 1;
        st[rr][t + 1] = (gi >= 0 && gi < Hh)
            ? 2.f * out0[b*HW + gi*Ww + t] - x_in[b*HW + gi*Ww + t] : 0.f;
    }
    __syncthreads();

    for (int f = 0; f < Fn; f++) {
        float wf[3][3];
        #pragma unroll
        for (int p = 0; p < 3; p++)
            #pragma unroll
            for (int q = 0; q < 3; q++)
                wf[p][q] = __ldg(&w[f*9 + p*3 + q]);

        float y[TR];
        #pragma unroll
        for (int r = 0; r < TR; r++) y[r] = 0.f;

        #pragma unroll
        for (int q = 0; q < 3; q++) {
            #pragma unroll
            for (int rr = 0; rr < TR + 2; rr++) {
                float v = st[rr][t + q];
                if (rr < TR)               y[rr]   = fmaf(wf[0][q], v, y[rr]);
                if (rr >= 1 && rr < TR+1)  y[rr-1] = fmaf(wf[1][q], v, y[rr-1]);
                if (rr >= 2)               y[rr-2] = fmaf(wf[2][q], v, y[rr-2]);
            }
        }

        #pragma unroll
        for (int r = 0; r < TR; r++) {
            int idx = ((b*Fn + f)*Hh + (i0 + r))*Ww + t;
            float o = sig * y[r] + u_in[idx];
            o = fminf(fmaxf(o, -lam), lam);
            out1[idx] = o;
        }
    }
}

// ---------------- launch ----------------------------------------------------
extern "C" void kernel_launch(void* const* d_in, const int* in_sizes, int n_in,
                              void* d_out, int out_size)
{
    const float* x_in  = (const float*)d_in[0];
    const float* u_in  = (const float*)d_in[1];
    const float* bias  = (const float*)d_in[2];
    const float* beta  = (const float*)d_in[3];
    const float* lambd = (const float*)d_in[4];
    const float* HtH   = (const float*)d_in[5];
    const float* w     = (const float*)d_in[6];
    const float* lsig  = (const float*)d_in[7];

    float* out0 = (float*)d_out;
    float* out1 = out0 + (size_t)Bn * HW;

    k_setup<<<129, 256>>>(w, beta, lambd, lsig);
    k_power<<<PBLK, 256>>>();
    k_pass1<<<256, 256>>>(x_in, u_in, bias, HtH, w, out0);
    k_pass2<<<256, 256>>>(x_in, u_in, w, out0, out1);
}

// round 2
// speedup vs baseline: 2.8001x; 2.8001x over previous
#include <cuda_runtime.h>

#define Hh 256
#define Ww 256
#define Bn 8
#define Fn 64
#define HW 65536
#define TR 8
#define PBLK 128

// ---------------- device globals -------------------------------------------
__device__ float g_xA[HW];
__device__ float g_xB[HW];
__device__ float4 g_part4[2][PBLK];
__device__ float g_K[81];
__device__ float g_G[25];
__device__ float g_p1[4][Bn * HW];       // pass1 filter-group partials (8MB)
__device__ float g_sigma, g_beta, g_lambda, g_tau, g_lip2;
__device__ unsigned g_barcnt = 0;        // invariant 0 between barriers
__device__ unsigned g_bargen = 0;        // monotone generation

// ---------------- setup ------------------------------------------------------
__global__ void k_setup(const float* __restrict__ w, const float* __restrict__ beta,
                        const float* __restrict__ lambd, const float* __restrict__ lsig)
{
    if (blockIdx.x == 0) {
        __shared__ float sK[81];
        int t = threadIdx.x;
        if (t < 81) {
            int a9 = t / 9, b9 = t % 9;
            int ai = a9 / 3, aj = a9 % 3;
            int bi = b9 / 3, bj = b9 % 3;
            float s = 0.f;
            #pragma unroll 8
            for (int f = 0; f < Fn; f++)
                s += w[f*9 + (2-ai)*3 + (2-aj)] * w[f*9 + bi*3 + bj];
            sK[t] = s;
            g_K[t] = s;
        }
        __syncthreads();
        if (t < 25) {
            int di = t / 5 - 2, dj = t % 5 - 2;
            float s = 0.f;
            for (int a9 = 0; a9 < 9; a9++) {
                int ai = a9/3 - 1, aj = a9%3 - 1;
                int bi = di - ai, bj = dj - aj;
                if (bi >= -1 && bi <= 1 && bj >= -1 && bj <= 1)
                    s += sK[a9*9 + (bi+1)*3 + (bj+1)];
            }
            g_G[t] = s;
        }
        if (t == 0) {
            g_sigma  = expf(lsig[0]) + 0.05f;
            g_beta   = beta[0];
            g_lambda = lambd[0];
        }
    } else {
        int p = (blockIdx.x - 1) * 512 + threadIdx.x;
        g_xA[p]       = 1.f / 256.f;
        g_xA[p + 256] = 1.f / 256.f;
    }
}

// ---------------- grid barrier (graph-replay safe) ---------------------------
__device__ __forceinline__ void grid_bar()
{
    __syncthreads();
    if (threadIdx.x == 0) {
        volatile unsigned* genp = &g_bargen;
        unsigned gen = *genp;
        unsigned a = atomicAdd(&g_barcnt, 1u);
        if (a == PBLK - 1u) {
            atomicExch(&g_barcnt, 0u);
            __threadfence();
            atomicExch(&g_bargen, gen + 1u);
        } else {
            while (*genp == gen) { __nanosleep(32); }
        }
        __threadfence();
    }
    __syncthreads();
}

// ---------------- one application of M on smem tiles --------------------------
// src rows cover [dst_lo_g-2, dst_lo_g+n+1] starting at smem row 0; both buffers
// have 2 zero pad columns each side (stride 260, data cols 2..257).
__device__ __forceinline__ void apply_app(
    const float* __restrict__ src, float* __restrict__ dst,
    int n, int dst_lo_g, int src_lo_g, int own_rr, int j,
    const float G[25], float* __restrict__ sacc, float* __restrict__ gdst)
{
    float win[5][5];
    #pragma unroll
    for (int r = 0; r < 4; r++)
        #pragma unroll
        for (int c = 0; c < 5; c++)
            win[r+1][c] = src[r*260 + j + c];

    #pragma unroll 2
    for (int rr = 0; rr < n; rr++) {
        const int r = dst_lo_g + rr;
        #pragma unroll
        for (int q = 0; q < 4; q++)
            #pragma unroll
            for (int c = 0; c < 5; c++)
                win[q][c] = win[q+1][c];
        #pragma unroll
        for (int c = 0; c < 5; c++)
            win[4][c] = src[(rr + 4)*260 + j + c];

        float z = 0.f;
        if (r >= 0 && r < 256) {
            #pragma unroll
            for (int di = 0; di < 5; di++)
                #pragma unroll
                for (int dj = 0; dj < 5; dj++)
                    z = fmaf(G[di*5 + dj], win[di][dj], z);
            if (r == 0 || r == 255 || j == 0 || j == 255) {
                #pragma unroll
                for (int ai = 0; ai < 3; ai++)
                    #pragma unroll
                    for (int aj = 0; aj < 3; aj++) {
                        int pi = r + ai - 1, pj = j + aj - 1;
                        if (pi < 0 || pi > 255 || pj < 0 || pj > 255) {
                            #pragma unroll
                            for (int bi = 0; bi < 3; bi++)
                                #pragma unroll
                                for (int bj = 0; bj < 3; bj++) {
                                    int qi = pi + bi - 1, qj = pj + bj - 1;
                                    if (qi >= 0 && qi < 256 && qj >= 0 && qj < 256)
                                        z -= __ldg(&g_K[(ai*3+aj)*9 + bi*3 + bj]) *
                                             src[(qi - src_lo_g)*260 + qj + 2];
                                }
                        }
                    }
            }
        }
        dst[rr*260 + 2 + j] = z;
        if (rr == own_rr || rr == own_rr + 1) {
            *sacc = fmaf(z, z, *sacc);
            if (gdst) gdst[r*256 + j] = z;
        }
    }
}

// ---------------- power iteration: 3 applications per grid barrier -----------
__global__ void __launch_bounds__(256, 1) k_power()
{
    __shared__ float bufA[14 * 260];
    __shared__ float bufB[10 * 260];
    __shared__ float red[3][8];
    const int t = threadIdx.x, blk = blockIdx.x;
    const int j = t, lane = t & 31, warp = t >> 5;
    const int i0 = blk * 2;

    float G[25];
    #pragma unroll
    for (int k = 0; k < 25; k++) G[k] = g_G[k];

    // zero pad columns (one-time; apps never write them)
    if (t < 14) { bufA[t*260] = bufA[t*260+1] = bufA[t*260+258] = bufA[t*260+259] = 0.f; }
    if (t >= 32 && t < 42) {
        int q = t - 32;
        bufB[q*260] = bufB[q*260+1] = bufB[q*260+258] = bufB[q*260+259] = 0.f;
    }

    float val = 1.f, inv = 1.f;
    int iter = 0, par = 0;
    bool done = false;

    while (!done) {
        const float* srcg = par ? g_xB : g_xA;
        float*       dstg = par ? g_xA : g_xB;

        __syncthreads();
        #pragma unroll
        for (int rr = 0; rr < 14; rr++) {
            int gi = i0 - 6 + rr;
            bufA[rr*260 + 2 + j] = (gi >= 0 && gi < 256) ? inv * __ldcg(&srcg[gi*256 + j]) : 0.f;
        }
        __syncthreads();

        float s1 = 0.f, s2 = 0.f, s3 = 0.f;
        apply_app(bufA, bufB, 10, i0 - 4, i0 - 6, 4, j, G, &s1, nullptr);
        __syncthreads();
        apply_app(bufB, bufA,  6, i0 - 2, i0 - 4, 2, j, G, &s2, nullptr);
        __syncthreads();
        apply_app(bufA, bufB,  2, i0,     i0 - 2, 0, j, G, &s3, dstg);

        // deterministic block reduce (fixed-order butterfly + fixed-order warp sum)
        #pragma unroll
        for (int o = 16; o > 0; o >>= 1) {
            s1 += __shfl_xor_sync(0xffffffffu, s1, o);
            s2 += __shfl_xor_sync(0xffffffffu, s2, o);
            s3 += __shfl_xor_sync(0xffffffffu, s3, o);
        }
        if (lane == 0) { red[0][warp] = s1; red[1][warp] = s2; red[2][warp] = s3; }
        __syncthreads();
        if (t == 0) {
            float a = 0.f, b = 0.f, c = 0.f;
            #pragma unroll
            for (int w8 = 0; w8 < 8; w8++) { a += red[0][w8]; b += red[1][w8]; c += red[2][w8]; }
            g_part4[par][blk] = make_float4(a, b, c, 0.f);
        }
        __threadfence();          // each thread flushes its dstg stores (and partial)
        grid_bar();

        // global fixed-order reduce of the 128 partials (identical on all blocks)
        float px = 0.f, py = 0.f, pz = 0.f;
        if (t < 128) {
            float4 p = *(const float4*)__builtin_assume_aligned(&g_part4[par][t], 16);
            // force L2 read
            p.x = __ldcg(&g_part4[par][t].x);
            p.y = __ldcg(&g_part4[par][t].y);
            p.z = __ldcg(&g_part4[par][t].z);
            px = p.x; py = p.y; pz = p.z;
        }
        #pragma unroll
        for (int o = 16; o > 0; o >>= 1) {
            px += __shfl_xor_sync(0xffffffffu, px, o);
            py += __shfl_xor_sync(0xffffffffu, py, o);
            pz += __shfl_xor_sync(0xffffffffu, pz, o);
        }
        __syncthreads();          // red reuse
        if (lane == 0 && t < 128) { red[0][warp] = px; red[1][warp] = py; red[2][warp] = pz; }
        __syncthreads();
        float S1 = red[0][0] + red[0][1] + red[0][2] + red[0][3];
        float S2 = red[1][0] + red[1][1] + red[1][2] + red[1][3];
        float S3 = red[2][0] + red[2][1] + red[2][2] + red[2][3];

        // replicate the reference's per-application stopping rule
        float v1 = sqrtf(S1);
        float v2 = sqrtf(S2) / v1;
        float v3 = sqrtf(S3) / sqrtf(S2);
        float rel;
        iter++; rel = fabsf(v1 - val) / val; val = v1;
        if (iter >= 300 || rel < 1e-4f) { done = true; }
        else {
            iter++; rel = fabsf(v2 - val) / val; val = v2;
            if (iter >= 300 || rel < 1e-4f) { done = true; }
            else {
                iter++; rel = fabsf(v3 - val) / val; val = v3;
                if (iter >= 300 || rel < 1e-4f) done = true;
            }
        }
        inv = 1.f / sqrtf(S3);
        par ^= 1;
    }

    if (blk == 0 && t == 0) {
        g_lip2 = val;
        g_tau  = 0.99f / (g_beta * 0.5f + g_sigma * val);
    }
}

// ---------------- pass 1 partials: 4 filter groups x 16 filters --------------
__global__ void k_pass1(const float* __restrict__ x_in,
                        const float* __restrict__ u_in,
                        const float* __restrict__ bias,
                        const float* __restrict__ HtH,
                        const float* __restrict__ w)
{
    __shared__ float su[TR + 2][Ww + 2];
    const int t    = threadIdx.x;
    const int fg   = blockIdx.x & 3;
    const int tile = (blockIdx.x >> 2) & 31;
    const int b    = blockIdx.x >> 7;
    const int i0   = tile * TR;
    const float tau = g_tau;

    float acc[TR];
    if (fg == 0) {
        #pragma unroll
        for (int r = 0; r < TR; r++) {
            int hw = (i0 + r) * Ww + t;
            float xv = x_in[b*HW + hw];
            acc[r] = xv - tau * (HtH[hw] * xv) + tau * bias[b*HW + hw];
        }
    } else {
        #pragma unroll
        for (int r = 0; r < TR; r++) acc[r] = 0.f;
    }
    if (t < TR + 2) { su[t][0] = 0.f; su[t][Ww + 1] = 0.f; }

    for (int ff = 0; ff < 16; ff++) {
        const int f = fg * 16 + ff;
        __syncthreads();
        #pragma unroll
        for (int rr = 0; rr < TR + 2; rr++) {
            int gi = i0 + rr - 1;
            su[rr][t + 1] = (gi >= 0 && gi < Hh)
                          ? u_in[((b*Fn + f)*Hh + gi)*Ww + t] : 0.f;
        }
        __syncthreads();

        float m[3][3];
        #pragma unroll
        for (int au = 0; au < 3; au++)
            #pragma unroll
            for (int ac = 0; ac < 3; ac++)
                m[au][ac] = tau * __ldg(&w[f*9 + (2-au)*3 + (2-ac)]);

        #pragma unroll
        for (int ac = 0; ac < 3; ac++) {
            #pragma unroll
            for (int rr = 0; rr < TR + 2; rr++) {
                float v = su[rr][t + ac];
                if (rr < TR)               acc[rr]   = fmaf(-m[0][ac], v, acc[rr]);
                if (rr >= 1 && rr < TR+1)  acc[rr-1] = fmaf(-m[1][ac], v, acc[rr-1]);
                if (rr >= 2)               acc[rr-2] = fmaf(-m[2][ac], v, acc[rr-2]);
            }
        }
    }

    #pragma unroll
    for (int r = 0; r < TR; r++)
        g_p1[fg][b*HW + (i0 + r)*Ww + t] = acc[r];
}

// ---------------- pass 1 combine ---------------------------------------------
__global__ void k_p1c(float* __restrict__ out0)
{
    int idx = blockIdx.x * 256 + threadIdx.x;   // float4 index, 512*256 = 131072 -> 524288 floats
    float4 a = ((const float4*)g_p1[0])[idx];
    float4 b = ((const float4*)g_p1[1])[idx];
    float4 c = ((const float4*)g_p1[2])[idx];
    float4 d = ((const float4*)g_p1[3])[idx];
    float4 r;
    r.x = fminf(fmaxf(a.x + b.x + c.x + d.x, 0.f), 1.f);
    r.y = fminf(fmaxf(a.y + b.y + c.y + d.y, 0.f), 1.f);
    r.z = fminf(fmaxf(a.z + b.z + c.z + d.z, 0.f), 1.f);
    r.w = fminf(fmaxf(a.w + b.w + c.w + d.w, 0.f), 1.f);
    ((float4*)out0)[idx] = r;
}

// ---------------- pass 2: 4 filter groups x 16 filters -----------------------
__global__ void k_pass2(const float* __restrict__ x_in,
                        const float* __restrict__ u_in,
                        const float* __restrict__ w,
                        const float* __restrict__ out0,
                        float* __restrict__ out1)
{
    __shared__ float st[TR + 2][Ww + 2];
    const int t    = threadIdx.x;
    const int fg   = blockIdx.x & 3;
    const int tile = (blockIdx.x >> 2) & 31;
    const int b    = blockIdx.x >> 7;
    const int i0   = tile * TR;
    const float sig = g_sigma, lam = g_lambda;

    if (t < TR + 2) { st[t][0] = 0.f; st[t][Ww + 1] = 0.f; }
    #pragma unroll
    for (int rr = 0; rr < TR + 2; rr++) {
        int gi = i0 + rr - 1;
        st[rr][t + 1] = (gi >= 0 && gi < Hh)
            ? 2.f * out0[b*HW + gi*Ww + t] - x_in[b*HW + gi*Ww + t] : 0.f;
    }
    __syncthreads();

    for (int ff = 0; ff < 16; ff++) {
        const int f = fg * 16 + ff;
        float wf[3][3];
        #pragma unroll
        for (int p = 0; p < 3; p++)
            #pragma unroll
            for (int q = 0; q < 3; q++)
                wf[p][q] = __ldg(&w[f*9 + p*3 + q]);

        float y[TR];
        #pragma unroll
        for (int r = 0; r < TR; r++) y[r] = 0.f;

        #pragma unroll
        for (int q = 0; q < 3; q++) {
            #pragma unroll
            for (int rr = 0; rr < TR + 2; rr++) {
                float v = st[rr][t + q];
                if (rr < TR)               y[rr]   = fmaf(wf[0][q], v, y[rr]);
                if (rr >= 1 && rr < TR+1)  y[rr-1] = fmaf(wf[1][q], v, y[rr-1]);
                if (rr >= 2)               y[rr-2] = fmaf(wf[2][q], v, y[rr-2]);
            }
        }

        #pragma unroll
        for (int r = 0; r < TR; r++) {
            int idx = ((b*Fn + f)*Hh + (i0 + r))*Ww + t;
            float o = sig * y[r] + u_in[idx];
            o = fminf(fmaxf(o, -lam), lam);
            out1[idx] = o;
        }
    }
}

// ---------------- launch ------------------------------------------------------
extern "C" void kernel_launch(void* const* d_in, const int* in_sizes, int n_in,
                              void* d_out, int out_size)
{
    const float* x_in  = (const float*)d_in[0];
    const float* u_in  = (const float*)d_in[1];
    const float* bias  = (const float*)d_in[2];
    const float* beta  = (const float*)d_in[3];
    const float* lambd = (const float*)d_in[4];
    const float* HtH   = (const float*)d_in[5];
    const float* w     = (const float*)d_in[6];
    const float* lsig  = (const float*)d_in[7];

    float* out0 = (float*)d_out;
    float* out1 = out0 + (size_t)Bn * HW;

    k_setup<<<129, 256>>>(w, beta, lambd, lsig);
    k_power<<<PBLK, 256>>>();
    k_pass1<<<1024, 256>>>(x_in, u_in, bias, HtH, w);
    k_p1c<<<512, 256>>>(out0);
    k_pass2<<<1024, 256>>>(x_in, u_in, w, out0, out1);
}